// round 1
// baseline (speedup 1.0000x reference)
#include <cuda_runtime.h>
#include <math.h>

// ---------------- problem constants ----------------
#define NC     32
#define NT     64
#define KU     2
#define BATCHN 4096
#define NITEM  (BATCHN*NC)      // 131072 (b,c) items
#define P_TGT  1.0f
#define EPSB   1e-5f

// MLP fused-kernel config
#define MLP_R   64              // rows per block
#define ACT_S   264             // smem row stride (bank-stagger, float4 aligned)
#define MLP_SMEM (2*MLP_R*ACT_S*4)

// ---------------- scratch (device globals; no allocation) ----------------
__device__ float4 d_FRF[BATCHN*NT];     // [b][t] = (f0.re,f0.im,f1.re,f1.im)   4MB
__device__ float2 d_Hc [NITEM*4];       // normalized H_equ [n][i*2+k]           4MB
__device__ float  d_x  [NITEM*8];       // MLP features                          4MB
__device__ float  d_mlp[NITEM*8];       // MLP outputs                           4MB
__device__ float  d_poly[NITEM*8];      // A,B,C,det0r,det0i,sr,si,pad           4MB
__device__ float  d_vp [NITEM*16];      // alpha[4] c, beta[4] c                 8MB
__device__ float2 d_V  [NITEM*4];       // final V [n][i*2+k]                    4MB
__device__ float  d_P  [NITEM];         // Power                                 0.5MB
__device__ float  d_partial[512];
__device__ float  d_state[4];           // lo, hi, unused, mu_final
__device__ int    d_it[1];

// ---------------- helpers ----------------
__device__ __forceinline__ float2 cmul(float2 a, float2 b) {
    return make_float2(a.x*b.x - a.y*b.y, a.x*b.y + a.y*b.x);
}
__device__ __forceinline__ float2 cadd(float2 a, float2 b){ return make_float2(a.x+b.x, a.y+b.y); }
__device__ __forceinline__ float2 csub(float2 a, float2 b){ return make_float2(a.x-b.x, a.y-b.y); }
__device__ __forceinline__ float2 conj2(float2 a){ return make_float2(a.x, -a.y); }
__device__ __forceinline__ float wred(float v){
    #pragma unroll
    for (int o = 16; o; o >>= 1) v += __shfl_down_sync(0xffffffffu, v, o);
    return v;
}

// ---------------- K1: F_RF ----------------
__global__ void k_frf(const float* __restrict__ H) {
    int warp = (blockIdx.x * blockDim.x + threadIdx.x) >> 5;
    int lane = threadIdx.x & 31;
    if (warp >= BATCHN) return;
    int b = warp;
    const float* r0 = H + ((b*2 + 0)*32 + 16)*128;
    const float* r1 = H + ((b*2 + 1)*32 + 16)*128;
    float im0 = r0[0];
    float im1 = r1[0];
    #pragma unroll
    for (int tt = 0; tt < 2; tt++) {
        int t = lane + tt*32;
        float re0 = r0[t], re1 = r1[t];
        float m0 = sqrtf(re0*re0 + im0*im0) * 8.0f;
        float m1 = sqrtf(re1*re1 + im1*im1) * 8.0f;
        float4 f;
        f.x =  re0 / m0;  f.y = -im0 / m0;
        f.z =  re1 / m1;  f.w = -im1 / m1;
        d_FRF[b*64 + t] = f;
    }
}

// ---------------- K2: H_equ (normalized) + features ----------------
__global__ void k_hequ(const float* __restrict__ H) {
    int warp = (blockIdx.x * blockDim.x + threadIdx.x) >> 5;
    int lane = threadIdx.x & 31;
    if (warp >= NITEM) return;
    int n = warp;
    int b = n >> 5, c = n & 31;
    int c3 = b >> 7;
    int b3 = ((b & 127) << 5) + c;

    float accr[2][2] = {{0,0},{0,0}};
    float acci[2][2] = {{0,0},{0,0}};
    #pragma unroll
    for (int i = 0; i < 2; i++) {
        int M  = c3*8192 + b3*2 + i;
        int bb = M >> 6, kk = (M >> 5) & 1, cc = M & 31;
        const float* row = H + ((bb*2 + kk)*32 + cc)*128;
        float him = row[0];
        #pragma unroll
        for (int tt = 0; tt < 2; tt++) {
            int t = lane + tt*32;
            float hre = row[t];
            float4 f = d_FRF[b3*64 + t];
            accr[i][0] += hre*f.x - him*f.y;
            acci[i][0] += hre*f.y + him*f.x;
            accr[i][1] += hre*f.z - him*f.w;
            acci[i][1] += hre*f.w + him*f.z;
        }
    }
    #pragma unroll
    for (int i = 0; i < 2; i++)
        #pragma unroll
        for (int k = 0; k < 2; k++) {
            accr[i][k] = wred(accr[i][k]);
            acci[i][k] = wred(acci[i][k]);
        }
    if (lane == 0) {
        float pw = 0.f;
        #pragma unroll
        for (int i = 0; i < 2; i++)
            #pragma unroll
            for (int k = 0; k < 2; k++)
                pw += accr[i][k]*accr[i][k] + acci[i][k]*acci[i][k];
        float inv = 1.0f / sqrtf(pw);
        #pragma unroll
        for (int i = 0; i < 2; i++)
            #pragma unroll
            for (int k = 0; k < 2; k++) {
                float re = accr[i][k]*inv, im = acci[i][k]*inv;
                d_Hc[n*4 + i*2 + k] = make_float2(re, im);
                d_x[n*8 + i*2 + k]     = re;
                d_x[n*8 + 4 + i*2 + k] = im;
            }
    }
}

// ---------------- K3: fused MLP 8->256->256->256->8 ----------------
__device__ __forceinline__ void layer256(const float* __restrict__ src, float* __restrict__ dst,
                                         const float* __restrict__ W, const float* __restrict__ bias,
                                         int t) {
    int cg = t & 63, rg = t >> 6;
    float acc[16][4];
    float4 bv = *(const float4*)(bias + cg*4);
    #pragma unroll
    for (int r = 0; r < 16; r++) { acc[r][0]=bv.x; acc[r][1]=bv.y; acc[r][2]=bv.z; acc[r][3]=bv.w; }
    const float* srcr = src + rg*16*ACT_S;
    for (int i = 0; i < 256; i += 4) {
        float4 w0 = *(const float4*)(W + (i  )*256 + cg*4);
        float4 w1 = *(const float4*)(W + (i+1)*256 + cg*4);
        float4 w2 = *(const float4*)(W + (i+2)*256 + cg*4);
        float4 w3 = *(const float4*)(W + (i+3)*256 + cg*4);
        #pragma unroll
        for (int r = 0; r < 16; r++) {
            float4 a = *(const float4*)(srcr + r*ACT_S + i);
            acc[r][0] += a.x*w0.x; acc[r][1] += a.x*w0.y; acc[r][2] += a.x*w0.z; acc[r][3] += a.x*w0.w;
            acc[r][0] += a.y*w1.x; acc[r][1] += a.y*w1.y; acc[r][2] += a.y*w1.z; acc[r][3] += a.y*w1.w;
            acc[r][0] += a.z*w2.x; acc[r][1] += a.z*w2.y; acc[r][2] += a.z*w2.z; acc[r][3] += a.z*w2.w;
            acc[r][0] += a.w*w3.x; acc[r][1] += a.w*w3.y; acc[r][2] += a.w*w3.z; acc[r][3] += a.w*w3.w;
        }
    }
    #pragma unroll
    for (int r = 0; r < 16; r++) {
        float4 o;
        o.x = fmaxf(acc[r][0], 0.f); o.y = fmaxf(acc[r][1], 0.f);
        o.z = fmaxf(acc[r][2], 0.f); o.w = fmaxf(acc[r][3], 0.f);
        *(float4*)(dst + (rg*16 + r)*ACT_S + cg*4) = o;
    }
}

__global__ __launch_bounds__(256) void k_mlp(const float* __restrict__ W0, const float* __restrict__ b0,
                                             const float* __restrict__ W1, const float* __restrict__ b1,
                                             const float* __restrict__ W2, const float* __restrict__ b2,
                                             const float* __restrict__ W3, const float* __restrict__ b3) {
    extern __shared__ float sm[];
    float* A = sm;
    float* B = sm + MLP_R*ACT_S;
    int t = threadIdx.x;
    int row0 = blockIdx.x * MLP_R;

    // stage inputs (64 rows x 8) into B (packed)
    for (int idx = t; idx < MLP_R*8; idx += 256) B[idx] = d_x[row0*8 + idx];
    __syncthreads();

    // L0: 8 -> 256, thread t owns column t for all rows
    {
        float w[8];
        #pragma unroll
        for (int i = 0; i < 8; i++) w[i] = W0[i*256 + t];
        float bs = b0[t];
        for (int r = 0; r < MLP_R; r++) {
            float acc = bs;
            #pragma unroll
            for (int i = 0; i < 8; i++) acc += B[r*8 + i] * w[i];
            A[r*ACT_S + t] = fmaxf(acc, 0.f);
        }
    }
    __syncthreads();
    layer256(A, B, W1, b1, t);  __syncthreads();
    layer256(B, A, W2, b2, t);  __syncthreads();

    // L3: 256 -> 8 (no relu)
    {
        int r = t >> 2, p = t & 3;
        const float* src = A + r*ACT_S;
        float a0 = b3[p*2], a1 = b3[p*2 + 1];
        for (int i = 0; i < 256; i += 4) {
            float4 v = *(const float4*)(src + i);
            a0 += v.x*W3[(i  )*8 + p*2] + v.y*W3[(i+1)*8 + p*2] + v.z*W3[(i+2)*8 + p*2] + v.w*W3[(i+3)*8 + p*2];
            a1 += v.x*W3[(i  )*8 + p*2+1] + v.y*W3[(i+1)*8 + p*2+1] + v.z*W3[(i+2)*8 + p*2+1] + v.w*W3[(i+3)*8 + p*2+1];
        }
        d_mlp[(row0 + r)*8 + p*2]     = a0;
        d_mlp[(row0 + r)*8 + p*2 + 1] = a1;
    }
}

// ---------------- K4: per-item bisection precomputes ----------------
__global__ void k_coef(void) {
    int n = blockIdx.x * blockDim.x + threadIdx.x;
    if (n >= NITEM) return;
    float m[8];
    #pragma unroll
    for (int j = 0; j < 8; j++) m[j] = d_mlp[n*8 + j];
    float2 h[2][2];
    #pragma unroll
    for (int k = 0; k < 2; k++)
        #pragma unroll
        for (int j = 0; j < 2; j++) h[k][j] = d_Hc[n*4 + k*2 + j];

    float2 U[2], Wm[2], UW[2], coef[2];
    #pragma unroll
    for (int k = 0; k < 2; k++) {
        U[k]  = make_float2(m[k],     m[2 + k]);
        Wm[k] = make_float2(m[4 + k], m[6 + k]);
        float au2 = U[k].x*U[k].x + U[k].y*U[k].y;
        coef[k] = make_float2(Wm[k].x*au2, Wm[k].y*au2);
        UW[k]   = cmul(U[k], Wm[k]);
    }
    float2 Bm[2][2] = {{{0,0},{0,0}},{{0,0},{0,0}}};
    #pragma unroll
    for (int k = 0; k < 2; k++)
        #pragma unroll
        for (int i = 0; i < 2; i++)
            #pragma unroll
            for (int j = 0; j < 2; j++)
                Bm[i][j] = cadd(Bm[i][j], cmul(coef[k], cmul(conj2(h[k][i]), h[k][j])));

    float2 a = Bm[0][0], bq = Bm[0][1], cq = Bm[1][0], dq = Bm[1][1];
    float2 hb[2][2];
    #pragma unroll
    for (int k = 0; k < 2; k++)
        #pragma unroll
        for (int j = 0; j < 2; j++) hb[k][j] = conj2(h[k][j]);

    float2 alpha[2][2], beta[2][2];
    #pragma unroll
    for (int k = 0; k < 2; k++) {
        float2 p0 = csub(cmul(dq, hb[k][0]), cmul(bq, hb[k][1]));
        float2 p1 = csub(cmul(a,  hb[k][1]), cmul(cq, hb[k][0]));
        alpha[0][k] = cmul(UW[k], p0);
        alpha[1][k] = cmul(UW[k], p1);
        beta[0][k]  = cmul(UW[k], hb[k][0]);
        beta[1][k]  = cmul(UW[k], hb[k][1]);
    }
    float2 det0 = csub(cmul(a, dq), cmul(bq, cq));
    float2 s    = cadd(a, dq);

    float A = 0.f, Bc = 0.f, Cc = 0.f;
    #pragma unroll
    for (int i = 0; i < 2; i++)
        #pragma unroll
        for (int k = 0; k < 2; k++) {
            A  += alpha[i][k].x*alpha[i][k].x + alpha[i][k].y*alpha[i][k].y;
            Bc += alpha[i][k].x*beta[i][k].x  + alpha[i][k].y*beta[i][k].y;
            Cc += beta[i][k].x*beta[i][k].x   + beta[i][k].y*beta[i][k].y;
        }
    Bc *= 4.f; Cc *= 4.f;

    float* pp = &d_poly[n*8];
    pp[0]=A; pp[1]=Bc; pp[2]=Cc; pp[3]=det0.x; pp[4]=det0.y; pp[5]=s.x; pp[6]=s.y; pp[7]=0.f;
    float* vp = &d_vp[n*16];
    #pragma unroll
    for (int i = 0; i < 2; i++)
        #pragma unroll
        for (int k = 0; k < 2; k++) {
            int e = i*2 + k;
            vp[e*2]     = alpha[i][k].x;  vp[e*2 + 1]     = alpha[i][k].y;
            vp[8 + e*2] = beta[i][k].x;   vp[8 + e*2 + 1] = beta[i][k].y;
        }
}

// ---------------- bisection ----------------
__global__ void k_init(void) {
    d_state[0] = 0.0f; d_state[1] = 10.0f; d_state[2] = 0.0f; d_state[3] = 5.0f;
    d_it[0] = 0;
}

__global__ void k_bisect(void) {
    __shared__ float sred[256];
    int n = blockIdx.x * 256 + threadIdx.x;
    float lo = d_state[0], hi = d_state[1];
    float mu = (lo + hi) * 0.5f;
    float val = 0.f;
    if (n < NITEM) {
        const float* pp = &d_poly[n*8];
        float A = pp[0], Bc = pp[1], Cc = pp[2];
        float dr = pp[3] + 2.f*mu*pp[5] + 4.f*mu*mu;
        float di = pp[4] + 2.f*mu*pp[6];
        val = (A + Bc*mu + Cc*mu*mu) / (dr*dr + di*di);
    }
    sred[threadIdx.x] = val;
    __syncthreads();
    for (int o = 128; o; o >>= 1) {
        if (threadIdx.x < o) sred[threadIdx.x] += sred[threadIdx.x + o];
        __syncthreads();
    }
    if (threadIdx.x == 0) d_partial[blockIdx.x] = sred[0];
}

__global__ void k_update(void) {
    __shared__ float sred[512];
    int t = threadIdx.x;
    sred[t] = d_partial[t];
    __syncthreads();
    for (int o = 256; o; o >>= 1) {
        if (t < o) sred[t] += sred[t + o];
        __syncthreads();
    }
    if (t == 0) {
        float lo = d_state[0], hi = d_state[1];
        int it = d_it[0];
        if (hi - lo >= EPSB && it <= 100) {
            float mu = (lo + hi) * 0.5f;
            float S  = sred[0];
            if (S > P_TGT) lo = mu; else hi = mu;
            d_state[0] = lo; d_state[1] = hi; d_state[3] = mu;
            d_it[0] = it + 1;
        }
    }
}

// ---------------- K6: final V ----------------
__global__ void k_vfinal(void) {
    int n = blockIdx.x * blockDim.x + threadIdx.x;
    if (n >= NITEM) return;
    float mu = d_state[3];
    const float* pp = &d_poly[n*8];
    float dr = pp[3] + 2.f*mu*pp[5] + 4.f*mu*mu;
    float di = pp[4] + 2.f*mu*pp[6];
    float den = dr*dr + di*di;
    float2 idet = make_float2(dr/den, -di/den);
    const float* vp = &d_vp[n*16];
    #pragma unroll
    for (int e = 0; e < 4; e++) {
        float2 al = make_float2(vp[e*2],     vp[e*2 + 1]);
        float2 be = make_float2(vp[8 + e*2], vp[8 + e*2 + 1]);
        float2 num = make_float2(al.x + 2.f*mu*be.x, al.y + 2.f*mu*be.y);
        d_V[n*4 + e] = cmul(num, idet);
    }
}

// ---------------- K7: Power (direct ||F_RF[bp] @ V[b,c]||^2) ----------------
__global__ void k_power(void) {
    int warp = (blockIdx.x * blockDim.x + threadIdx.x) >> 5;
    int lane = threadIdx.x & 31;
    if (warp >= NITEM) return;
    int n = warp;
    int b = n >> 5, c = n & 31;
    int bp = ((b & 127) << 5) + c;
    float2 v[2][2];
    #pragma unroll
    for (int i = 0; i < 2; i++)
        #pragma unroll
        for (int k = 0; k < 2; k++) v[i][k] = d_V[n*4 + i*2 + k];
    float acc = 0.f;
    #pragma unroll
    for (int tt = 0; tt < 2; tt++) {
        int t = lane + tt*32;
        float4 f = d_FRF[bp*64 + t];
        #pragma unroll
        for (int k = 0; k < 2; k++) {
            float orr = f.x*v[0][k].x - f.y*v[0][k].y + f.z*v[1][k].x - f.w*v[1][k].y;
            float oii = f.x*v[0][k].y + f.y*v[0][k].x + f.z*v[1][k].y + f.w*v[1][k].x;
            acc += orr*orr + oii*oii;
        }
    }
    acc = wred(acc);
    if (lane == 0) d_P[n] = acc;
}

// ---------------- K8: final output ----------------
__global__ void k_out(float* __restrict__ out) {
    int warp = (blockIdx.x * blockDim.x + threadIdx.x) >> 5;
    int lane = threadIdx.x & 31;
    if (warp >= NITEM) return;
    int n = warp;
    int b = n >> 5, c = n & 31;
    int bv = c*128 + (b >> 5);
    int cv = b & 31;
    int nv = bv*32 + cv;
    float Pw = d_P[n];
    float sc = sqrtf(2.0f) / sqrtf(Pw);
    float2 v[2][2];
    #pragma unroll
    for (int i = 0; i < 2; i++)
        #pragma unroll
        for (int k = 0; k < 2; k++) {
            float2 t2 = d_V[nv*4 + i*2 + k];
            v[i][k] = make_float2(t2.x*sc, t2.y*sc);
        }
    float* outre = out + (size_t)b*8192 + c*128;
    float* outim = outre + 4096;
    #pragma unroll
    for (int tt = 0; tt < 2; tt++) {
        int t = lane + tt*32;
        float4 f = d_FRF[b*64 + t];
        float o0r = f.x*v[0][0].x - f.y*v[0][0].y + f.z*v[1][0].x - f.w*v[1][0].y;
        float o0i = f.x*v[0][0].y + f.y*v[0][0].x + f.z*v[1][0].y + f.w*v[1][0].x;
        float o1r = f.x*v[0][1].x - f.y*v[0][1].y + f.z*v[1][1].x - f.w*v[1][1].y;
        float o1i = f.x*v[0][1].y + f.y*v[0][1].x + f.z*v[1][1].y + f.w*v[1][1].x;
        ((float2*)outre)[t] = make_float2(o0r, o1r);
        ((float2*)outim)[t] = make_float2(o0i, o1i);
    }
}

// ---------------- launch ----------------
extern "C" void kernel_launch(void* const* d_in, const int* in_sizes, int n_in,
                              void* d_out, int out_size) {
    (void)in_sizes; (void)n_in; (void)out_size;
    const float* H  = (const float*)d_in[0];
    const float* W0 = (const float*)d_in[1];
    const float* b0 = (const float*)d_in[2];
    const float* W1 = (const float*)d_in[3];
    const float* b1 = (const float*)d_in[4];
    const float* W2 = (const float*)d_in[5];
    const float* b2 = (const float*)d_in[6];
    const float* W3 = (const float*)d_in[7];
    const float* b3 = (const float*)d_in[8];
    float* out = (float*)d_out;

    cudaFuncSetAttribute(k_mlp, cudaFuncAttributeMaxDynamicSharedMemorySize, MLP_SMEM);

    k_frf <<<BATCHN*32/256, 256>>>(H);
    k_hequ<<<NITEM*32/256,  256>>>(H);
    k_mlp <<<NITEM/MLP_R, 256, MLP_SMEM>>>(W0, b0, W1, b1, W2, b2, W3, b3);
    k_coef<<<NITEM/256, 256>>>();
    k_init<<<1, 1>>>();
    for (int it = 0; it < 21; it++) {
        k_bisect<<<512, 256>>>();
        k_update<<<1, 512>>>();
    }
    k_vfinal<<<NITEM/256, 256>>>();
    k_power <<<NITEM*32/256, 256>>>();
    k_out   <<<NITEM*32/256, 256>>>(out);
}

// round 2
// speedup vs baseline: 1.2105x; 1.2105x over previous
#include <cuda_runtime.h>
#include <math.h>

// ---------------- problem constants ----------------
#define NC     32
#define NT     64
#define BATCHN 4096
#define NITEM  (BATCHN*NC)      // 131072 (b,c) items
#define P_TGT  1.0f
#define EPSB   1e-5f

// MLP fused-kernel config
#define MLP_R   64              // rows per block
#define ACT_S   264             // smem row stride (float4 aligned)
#define MLP_SMEM (2*MLP_R*ACT_S*4)
#define MLP_T   512

// bisection config
#define BGRD 512
#define BBLK 256

// ---------------- scratch (device globals; no allocation) ----------------
__device__ float4 d_FRF[BATCHN*NT];
__device__ float2 d_Hc [NITEM*4];
__device__ float  d_x  [NITEM*8];
__device__ float  d_mlp[NITEM*8];
__device__ float  d_poly[NITEM*8];      // A,B,C,det0r,det0i,sr,si,pad
__device__ float  d_vp [NITEM*16];      // alpha[4] c, beta[4] c
__device__ float2 d_V  [NITEM*4];
__device__ float  d_P  [NITEM];
__device__ float  d_W1p[256*256];       // k-pair-packed weights
__device__ float  d_W2p[256*256];
__device__ float  d_part5[BGRD*31];
__device__ float  d_state[4];           // lo, hi, unused, mu
__device__ int    d_it[1];
__device__ int    d_cnt;

// ---------------- helpers ----------------
__device__ __forceinline__ float2 cmul(float2 a, float2 b) {
    return make_float2(a.x*b.x - a.y*b.y, a.x*b.y + a.y*b.x);
}
__device__ __forceinline__ float2 cadd(float2 a, float2 b){ return make_float2(a.x+b.x, a.y+b.y); }
__device__ __forceinline__ float2 csub(float2 a, float2 b){ return make_float2(a.x-b.x, a.y-b.y); }
__device__ __forceinline__ float2 conj2(float2 a){ return make_float2(a.x, -a.y); }
__device__ __forceinline__ float wred(float v){
    #pragma unroll
    for (int o = 16; o; o >>= 1) v += __shfl_down_sync(0xffffffffu, v, o);
    return v;
}
__device__ __forceinline__ unsigned long long fma2(unsigned long long a, unsigned long long b, unsigned long long c){
    unsigned long long d;
    asm("fma.rn.f32x2 %0, %1, %2, %3;" : "=l"(d) : "l"(a), "l"(b), "l"(c));
    return d;
}
__device__ __forceinline__ unsigned long long pk2(float x, float y){
    unsigned long long r; asm("mov.b64 %0, {%1, %2};" : "=l"(r) : "f"(x), "f"(y)); return r;
}
__device__ __forceinline__ float2 up2(unsigned long long v){
    float2 r; asm("mov.b64 {%0, %1}, %2;" : "=f"(r.x), "=f"(r.y) : "l"(v)); return r;
}

// ---------------- K0: bisection state init ----------------
__global__ void k_init(void) {
    d_state[0] = 0.0f; d_state[1] = 10.0f; d_state[2] = 0.0f; d_state[3] = 5.0f;
    d_it[0] = 0; d_cnt = 0;
}

// ---------------- K1: F_RF ----------------
__global__ void k_frf(const float* __restrict__ H) {
    int warp = (blockIdx.x * blockDim.x + threadIdx.x) >> 5;
    int lane = threadIdx.x & 31;
    if (warp >= BATCHN) return;
    int b = warp;
    const float* r0 = H + ((b*2 + 0)*32 + 16)*128;
    const float* r1 = H + ((b*2 + 1)*32 + 16)*128;
    float im0 = r0[0];
    float im1 = r1[0];
    #pragma unroll
    for (int tt = 0; tt < 2; tt++) {
        int t = lane + tt*32;
        float re0 = r0[t], re1 = r1[t];
        float m0 = sqrtf(re0*re0 + im0*im0) * 8.0f;
        float m1 = sqrtf(re1*re1 + im1*im1) * 8.0f;
        float4 f;
        f.x =  re0 / m0;  f.y = -im0 / m0;
        f.z =  re1 / m1;  f.w = -im1 / m1;
        d_FRF[b*64 + t] = f;
    }
}

// ---------------- K1b: weight k-pair repack ----------------
// dst[((k>>1)*256 + c)*2 + (k&1)] = src[k*256 + c]
__global__ void k_wpack(const float* __restrict__ src, float* __restrict__ dst) {
    int idx = blockIdx.x * blockDim.x + threadIdx.x;
    if (idx >= 256*256) return;
    int k = idx >> 8, c = idx & 255;
    dst[(((k >> 1)*256 + c) << 1) + (k & 1)] = src[idx];
}

// ---------------- K2: H_equ (normalized) + features ----------------
__global__ void k_hequ(const float* __restrict__ H) {
    int warp = (blockIdx.x * blockDim.x + threadIdx.x) >> 5;
    int lane = threadIdx.x & 31;
    if (warp >= NITEM) return;
    int n = warp;
    int b = n >> 5, c = n & 31;
    int c3 = b >> 7;
    int b3 = ((b & 127) << 5) + c;

    float accr[2][2] = {{0,0},{0,0}};
    float acci[2][2] = {{0,0},{0,0}};
    #pragma unroll
    for (int i = 0; i < 2; i++) {
        int M  = c3*8192 + b3*2 + i;
        int bb = M >> 6, kk = (M >> 5) & 1, cc = M & 31;
        const float* row = H + ((bb*2 + kk)*32 + cc)*128;
        float him = row[0];
        #pragma unroll
        for (int tt = 0; tt < 2; tt++) {
            int t = lane + tt*32;
            float hre = row[t];
            float4 f = d_FRF[b3*64 + t];
            accr[i][0] += hre*f.x - him*f.y;
            acci[i][0] += hre*f.y + him*f.x;
            accr[i][1] += hre*f.z - him*f.w;
            acci[i][1] += hre*f.w + him*f.z;
        }
    }
    #pragma unroll
    for (int i = 0; i < 2; i++)
        #pragma unroll
        for (int k = 0; k < 2; k++) {
            accr[i][k] = wred(accr[i][k]);
            acci[i][k] = wred(acci[i][k]);
        }
    if (lane == 0) {
        float pw = 0.f;
        #pragma unroll
        for (int i = 0; i < 2; i++)
            #pragma unroll
            for (int k = 0; k < 2; k++)
                pw += accr[i][k]*accr[i][k] + acci[i][k]*acci[i][k];
        float inv = 1.0f / sqrtf(pw);
        #pragma unroll
        for (int i = 0; i < 2; i++)
            #pragma unroll
            for (int k = 0; k < 2; k++) {
                float re = accr[i][k]*inv, im = acci[i][k]*inv;
                d_Hc[n*4 + i*2 + k] = make_float2(re, im);
                d_x[n*8 + i*2 + k]     = re;
                d_x[n*8 + 4 + i*2 + k] = im;
            }
    }
}

// ---------------- K3: fused MLP 8->256->256->256->8 (FFMA2) ----------------
// k-parity paired accumulation: acc halves hold sum over even k / odd k.
__device__ __forceinline__ void layer256_f2(const float* __restrict__ src, float* __restrict__ dst,
                                            const float* __restrict__ Wp, const float* __restrict__ bias,
                                            int t) {
    int cg = t & 63, rg = t >> 6;            // 64 col-groups x 8 row-groups
    unsigned long long acc[8][4];
    float4 bv = *(const float4*)(bias + cg*4);
    #pragma unroll
    for (int r = 0; r < 8; r++) {
        acc[r][0] = pk2(bv.x, 0.f); acc[r][1] = pk2(bv.y, 0.f);
        acc[r][2] = pk2(bv.z, 0.f); acc[r][3] = pk2(bv.w, 0.f);
    }
    const float* srcr  = src + rg*8*ACT_S;
    const float* wbase = Wp + cg*8;
    #pragma unroll 2
    for (int k = 0; k < 256; k += 4) {
        const float* wk = wbase + (k >> 1)*512;
        ulonglong2 w0a = *(const ulonglong2*)(wk);         // pair k/k+1, cols c0,c1
        ulonglong2 w0b = *(const ulonglong2*)(wk + 4);     // pair k/k+1, cols c2,c3
        ulonglong2 w1a = *(const ulonglong2*)(wk + 512);   // pair k+2/k+3, cols c0,c1
        ulonglong2 w1b = *(const ulonglong2*)(wk + 516);
        #pragma unroll
        for (int r = 0; r < 8; r++) {
            ulonglong2 aa = *(const ulonglong2*)(srcr + r*ACT_S + k);
            acc[r][0] = fma2(aa.x, w0a.x, acc[r][0]);
            acc[r][1] = fma2(aa.x, w0a.y, acc[r][1]);
            acc[r][2] = fma2(aa.x, w0b.x, acc[r][2]);
            acc[r][3] = fma2(aa.x, w0b.y, acc[r][3]);
            acc[r][0] = fma2(aa.y, w1a.x, acc[r][0]);
            acc[r][1] = fma2(aa.y, w1a.y, acc[r][1]);
            acc[r][2] = fma2(aa.y, w1b.x, acc[r][2]);
            acc[r][3] = fma2(aa.y, w1b.y, acc[r][3]);
        }
    }
    #pragma unroll
    for (int r = 0; r < 8; r++) {
        float2 s0 = up2(acc[r][0]), s1 = up2(acc[r][1]), s2 = up2(acc[r][2]), s3 = up2(acc[r][3]);
        float4 o;
        o.x = fmaxf(s0.x + s0.y, 0.f); o.y = fmaxf(s1.x + s1.y, 0.f);
        o.z = fmaxf(s2.x + s2.y, 0.f); o.w = fmaxf(s3.x + s3.y, 0.f);
        *(float4*)(dst + (rg*8 + r)*ACT_S + cg*4) = o;
    }
}

__global__ __launch_bounds__(MLP_T, 1) void k_mlp(const float* __restrict__ W0, const float* __restrict__ b0,
                                                  const float* __restrict__ b1,
                                                  const float* __restrict__ b2,
                                                  const float* __restrict__ W3, const float* __restrict__ b3) {
    extern __shared__ float sm[];
    float* A = sm;
    float* B = sm + MLP_R*ACT_S;
    int t = threadIdx.x;
    int row0 = blockIdx.x * MLP_R;

    // stage inputs (64 rows x 8) into B (packed)
    for (int idx = t; idx < MLP_R*8; idx += MLP_T) B[idx] = d_x[row0*8 + idx];
    __syncthreads();

    // L0: 8 -> 256. thread owns one column for 32 rows.
    {
        int col = t & 255, half = t >> 8;
        float w[8];
        #pragma unroll
        for (int i = 0; i < 8; i++) w[i] = W0[i*256 + col];
        float bs = b0[col];
        for (int r = half*32; r < half*32 + 32; r++) {
            float acc = bs;
            #pragma unroll
            for (int i = 0; i < 8; i++) acc += B[r*8 + i] * w[i];
            A[r*ACT_S + col] = fmaxf(acc, 0.f);
        }
    }
    __syncthreads();
    layer256_f2(A, B, d_W1p, b1, t);  __syncthreads();
    layer256_f2(B, A, d_W2p, b2, t);  __syncthreads();

    // L3: 256 -> 8 (no relu). thread t: row t>>3, output elem t&7.
    {
        int r = t >> 3, p = t & 7;
        const float* srcp = A + r*ACT_S;
        float acc = b3[p];
        for (int i = 0; i < 256; i += 4) {
            float4 v = *(const float4*)(srcp + i);
            acc += v.x*W3[(i  )*8 + p] + v.y*W3[(i+1)*8 + p]
                 + v.z*W3[(i+2)*8 + p] + v.w*W3[(i+3)*8 + p];
        }
        d_mlp[(row0 + r)*8 + p] = acc;
    }
}

// ---------------- K4: per-item bisection precomputes ----------------
__global__ void k_coef(void) {
    int n = blockIdx.x * blockDim.x + threadIdx.x;
    if (n >= NITEM) return;
    float m[8];
    #pragma unroll
    for (int j = 0; j < 8; j++) m[j] = d_mlp[n*8 + j];
    float2 h[2][2];
    #pragma unroll
    for (int k = 0; k < 2; k++)
        #pragma unroll
        for (int j = 0; j < 2; j++) h[k][j] = d_Hc[n*4 + k*2 + j];

    float2 U[2], Wm[2], UW[2], coef[2];
    #pragma unroll
    for (int k = 0; k < 2; k++) {
        U[k]  = make_float2(m[k],     m[2 + k]);
        Wm[k] = make_float2(m[4 + k], m[6 + k]);
        float au2 = U[k].x*U[k].x + U[k].y*U[k].y;
        coef[k] = make_float2(Wm[k].x*au2, Wm[k].y*au2);
        UW[k]   = cmul(U[k], Wm[k]);
    }
    float2 Bm[2][2] = {{{0,0},{0,0}},{{0,0},{0,0}}};
    #pragma unroll
    for (int k = 0; k < 2; k++)
        #pragma unroll
        for (int i = 0; i < 2; i++)
            #pragma unroll
            for (int j = 0; j < 2; j++)
                Bm[i][j] = cadd(Bm[i][j], cmul(coef[k], cmul(conj2(h[k][i]), h[k][j])));

    float2 a = Bm[0][0], bq = Bm[0][1], cq = Bm[1][0], dq = Bm[1][1];
    float2 hb[2][2];
    #pragma unroll
    for (int k = 0; k < 2; k++)
        #pragma unroll
        for (int j = 0; j < 2; j++) hb[k][j] = conj2(h[k][j]);

    float2 alpha[2][2], beta[2][2];
    #pragma unroll
    for (int k = 0; k < 2; k++) {
        float2 p0 = csub(cmul(dq, hb[k][0]), cmul(bq, hb[k][1]));
        float2 p1 = csub(cmul(a,  hb[k][1]), cmul(cq, hb[k][0]));
        alpha[0][k] = cmul(UW[k], p0);
        alpha[1][k] = cmul(UW[k], p1);
        beta[0][k]  = cmul(UW[k], hb[k][0]);
        beta[1][k]  = cmul(UW[k], hb[k][1]);
    }
    float2 det0 = csub(cmul(a, dq), cmul(bq, cq));
    float2 s    = cadd(a, dq);

    float A = 0.f, Bc = 0.f, Cc = 0.f;
    #pragma unroll
    for (int i = 0; i < 2; i++)
        #pragma unroll
        for (int k = 0; k < 2; k++) {
            A  += alpha[i][k].x*alpha[i][k].x + alpha[i][k].y*alpha[i][k].y;
            Bc += alpha[i][k].x*beta[i][k].x  + alpha[i][k].y*beta[i][k].y;
            Cc += beta[i][k].x*beta[i][k].x   + beta[i][k].y*beta[i][k].y;
        }
    Bc *= 4.f; Cc *= 4.f;

    float* pp = &d_poly[n*8];
    pp[0]=A; pp[1]=Bc; pp[2]=Cc; pp[3]=det0.x; pp[4]=det0.y; pp[5]=s.x; pp[6]=s.y; pp[7]=0.f;
    float* vp = &d_vp[n*16];
    #pragma unroll
    for (int i = 0; i < 2; i++)
        #pragma unroll
        for (int k = 0; k < 2; k++) {
            int e = i*2 + k;
            vp[e*2]     = alpha[i][k].x;  vp[e*2 + 1]     = alpha[i][k].y;
            vp[8 + e*2] = beta[i][k].x;   vp[8 + e*2 + 1] = beta[i][k].y;
        }
}

// ---------------- K5: 5 bisection levels per launch (31-candidate tree) ----------------
__global__ __launch_bounds__(BBLK) void k_bisect5(void) {
    float lo = d_state[0], hi = d_state[1];
    // heap-ordered bisection tree: node 1 = (lo,hi); 2n left, 2n+1 right
    float L[32], Hh[32], MU[32];
    L[1] = lo; Hh[1] = hi;
    #pragma unroll
    for (int nn = 1; nn < 32; nn++) {
        MU[nn] = (L[nn] + Hh[nn]) * 0.5f;
        if (nn < 16) {
            L[2*nn] = L[nn];  Hh[2*nn] = MU[nn];
            L[2*nn+1] = MU[nn]; Hh[2*nn+1] = Hh[nn];
        }
    }
    int n = blockIdx.x * BBLK + threadIdx.x;
    const float* pp = &d_poly[n*8];
    float A = pp[0], Bc = pp[1], Cc = pp[2], d0r = pp[3], d0i = pp[4], sr = pp[5], si = pp[6];
    float val[31];
    #pragma unroll
    for (int j = 0; j < 31; j++) {
        float mu = MU[j + 1];
        float dr = d0r + 2.f*mu*sr + 4.f*mu*mu;
        float di = d0i + 2.f*mu*si;
        val[j] = (A + Bc*mu + Cc*mu*mu) / (dr*dr + di*di);
    }
    #pragma unroll
    for (int j = 0; j < 31; j++)
        #pragma unroll
        for (int o = 16; o; o >>= 1) val[j] += __shfl_down_sync(0xffffffffu, val[j], o);

    __shared__ float sm[8*31];
    int w = threadIdx.x >> 5, lane = threadIdx.x & 31;
    if (lane == 0) {
        #pragma unroll
        for (int j = 0; j < 31; j++) sm[w*31 + j] = val[j];
    }
    __syncthreads();
    if (threadIdx.x < 31) {
        float s = 0.f;
        #pragma unroll
        for (int w2 = 0; w2 < 8; w2++) s += sm[w2*31 + threadIdx.x];
        d_part5[blockIdx.x*31 + threadIdx.x] = s;
    }
    __threadfence();
    __shared__ int isLast;
    if (threadIdx.x == 0) isLast = (atomicAdd(&d_cnt, 1) == BGRD - 1);
    __syncthreads();
    if (!isLast) return;

    // last block: global sums + resolve 5 bisection steps
    if (threadIdx.x < 31) {
        float s = 0.f;
        for (int bb = 0; bb < BGRD; bb++) s += d_part5[bb*31 + threadIdx.x];
        sm[threadIdx.x] = s;
    }
    __syncthreads();
    if (threadIdx.x == 0) {
        d_cnt = 0;
        float llo = lo, lhi = hi, mu = d_state[3];
        int it = d_it[0];
        int nid = 1;
        #pragma unroll
        for (int s5 = 0; s5 < 5; s5++) {
            if (lhi - llo >= EPSB && it <= 100) {
                mu = MU[nid];
                float S = sm[nid - 1];
                if (S > P_TGT) { llo = mu; nid = 2*nid + 1; }
                else           { lhi = mu; nid = 2*nid;     }
                it++;
            }
        }
        d_state[0] = llo; d_state[1] = lhi; d_state[3] = mu;
        d_it[0] = it;
    }
}

// ---------------- K6: final V + Power (fused) ----------------
__global__ void k_powv(void) {
    int warp = (blockIdx.x * blockDim.x + threadIdx.x) >> 5;
    int lane = threadIdx.x & 31;
    if (warp >= NITEM) return;
    int n = warp;
    int b = n >> 5, c = n & 31;
    int bp = ((b & 127) << 5) + c;
    float mu = d_state[3];
    const float* pp = &d_poly[n*8];
    float dr = pp[3] + 2.f*mu*pp[5] + 4.f*mu*mu;
    float di = pp[4] + 2.f*mu*pp[6];
    float den = dr*dr + di*di;
    float2 idet = make_float2(dr/den, -di/den);
    const float* vp = &d_vp[n*16];
    float2 v[2][2];
    #pragma unroll
    for (int i = 0; i < 2; i++)
        #pragma unroll
        for (int k = 0; k < 2; k++) {
            int e = i*2 + k;
            float2 al = make_float2(vp[e*2],     vp[e*2 + 1]);
            float2 be = make_float2(vp[8 + e*2], vp[8 + e*2 + 1]);
            float2 num = make_float2(al.x + 2.f*mu*be.x, al.y + 2.f*mu*be.y);
            v[i][k] = cmul(num, idet);
        }
    float acc = 0.f;
    #pragma unroll
    for (int tt = 0; tt < 2; tt++) {
        int t = lane + tt*32;
        float4 f = d_FRF[bp*64 + t];
        #pragma unroll
        for (int k = 0; k < 2; k++) {
            float orr = f.x*v[0][k].x - f.y*v[0][k].y + f.z*v[1][k].x - f.w*v[1][k].y;
            float oii = f.x*v[0][k].y + f.y*v[0][k].x + f.z*v[1][k].y + f.w*v[1][k].x;
            acc += orr*orr + oii*oii;
        }
    }
    acc = wred(acc);
    if (lane == 0) {
        d_P[n] = acc;
        #pragma unroll
        for (int e = 0; e < 4; e++) d_V[n*4 + e] = v[e >> 1][e & 1];
    }
}

// ---------------- K7: final output ----------------
__global__ void k_out(float* __restrict__ out) {
    int warp = (blockIdx.x * blockDim.x + threadIdx.x) >> 5;
    int lane = threadIdx.x & 31;
    if (warp >= NITEM) return;
    int n = warp;
    int b = n >> 5, c = n & 31;
    int bv = c*128 + (b >> 5);
    int cv = b & 31;
    int nv = bv*32 + cv;
    float Pw = d_P[n];
    float sc = sqrtf(2.0f) / sqrtf(Pw);
    float2 v[2][2];
    #pragma unroll
    for (int i = 0; i < 2; i++)
        #pragma unroll
        for (int k = 0; k < 2; k++) {
            float2 t2 = d_V[nv*4 + i*2 + k];
            v[i][k] = make_float2(t2.x*sc, t2.y*sc);
        }
    float* outre = out + (size_t)b*8192 + c*128;
    float* outim = outre + 4096;
    #pragma unroll
    for (int tt = 0; tt < 2; tt++) {
        int t = lane + tt*32;
        float4 f = d_FRF[b*64 + t];
        float o0r = f.x*v[0][0].x - f.y*v[0][0].y + f.z*v[1][0].x - f.w*v[1][0].y;
        float o0i = f.x*v[0][0].y + f.y*v[0][0].x + f.z*v[1][0].y + f.w*v[1][0].x;
        float o1r = f.x*v[0][1].x - f.y*v[0][1].y + f.z*v[1][1].x - f.w*v[1][1].y;
        float o1i = f.x*v[0][1].y + f.y*v[0][1].x + f.z*v[1][1].y + f.w*v[1][1].x;
        ((float2*)outre)[t] = make_float2(o0r, o1r);
        ((float2*)outim)[t] = make_float2(o0i, o1i);
    }
}

// ---------------- launch ----------------
extern "C" void kernel_launch(void* const* d_in, const int* in_sizes, int n_in,
                              void* d_out, int out_size) {
    (void)in_sizes; (void)n_in; (void)out_size;
    const float* H  = (const float*)d_in[0];
    const float* W0 = (const float*)d_in[1];
    const float* b0 = (const float*)d_in[2];
    const float* W1 = (const float*)d_in[3];
    const float* b1 = (const float*)d_in[4];
    const float* W2 = (const float*)d_in[5];
    const float* b2 = (const float*)d_in[6];
    const float* W3 = (const float*)d_in[7];
    const float* b3 = (const float*)d_in[8];
    float* out = (float*)d_out;

    cudaFuncSetAttribute(k_mlp, cudaFuncAttributeMaxDynamicSharedMemorySize, MLP_SMEM);

    float* w1p; cudaGetSymbolAddress((void**)&w1p, d_W1p);
    float* w2p; cudaGetSymbolAddress((void**)&w2p, d_W2p);

    k_init  <<<1, 1>>>();
    k_frf   <<<BATCHN*32/256, 256>>>(H);
    k_wpack <<<256, 256>>>(W1, w1p);
    k_wpack <<<256, 256>>>(W2, w2p);
    k_hequ  <<<NITEM*32/256, 256>>>(H);
    k_mlp   <<<NITEM/MLP_R, MLP_T, MLP_SMEM>>>(W0, b0, b1, b2, W3, b3);   // launch #6 -> ncu target
    k_coef  <<<NITEM/256, 256>>>();
    for (int it = 0; it < 4; it++)
        k_bisect5<<<BGRD, BBLK>>>();
    k_powv  <<<NITEM*32/256, 256>>>();
    k_out   <<<NITEM*32/256, 256>>>(out);
}